// round 10
// baseline (speedup 1.0000x reference)
#include <cuda_runtime.h>
#include <cstdint>
#include <cstddef>

// ---------------- problem constants ----------------
#define Q_ROWS  4096
#define N_ROWS  50000
#define K_CODES 1024
#define D_DIM   256
#define NTILES_N 391                 // ceil(50000/128)
#define QN ((size_t)Q_ROWS * N_ROWS)

// ---------------- argmin GEMM tiling ----------------
#define TILE_M   128
#define TILE_K   128
#define DCHUNK   32
#define NDCHUNK  (D_DIM / DCHUNK)    // 8
#define ROWSTRIDE 36
#define STAGE_F  (2 * TILE_M * ROWSTRIDE)     // 9216 floats per stage (A+B)
#define GEMM_SMEM_F (2 * STAGE_F + K_CODES)
#define GEMM_SMEM_B (GEMM_SMEM_F * 4)         // 77824 B

// ---------------- fused S+gather tiling ----------------
#define FQ 16                          // q rows per block
#define FS_AQ_F   (FQ * D_DIM)         // 4096 floats (16 KB)
#define FS_BROW   20                   // padded floats per Bbuf code row
#define FS_BBUF_F (K_CODES * FS_BROW)  // 20480 floats (80 KB)
#define FS_SMEM_F (FS_AQ_F + FS_BBUF_F)
#define FS_SMEM_B (FS_SMEM_F * 4)      // 98304 B (S[16x1024]=64KB overlays Bbuf)

// ---------------- small helpers ----------------
__device__ __forceinline__ uint32_t smem_u32(const void* p) {
    uint32_t a;
    asm("{ .reg .u64 t; cvta.to.shared.u64 t, %1; cvt.u32.u64 %0, t; }" : "=r"(a) : "l"(p));
    return a;
}
__device__ __forceinline__ void cpa16(uint32_t dst, const void* src, int szbytes) {
    asm volatile("cp.async.cg.shared.global [%0], [%1], 16, %2;\n"
                 :: "r"(dst), "l"(src), "r"(szbytes));
}
__device__ __forceinline__ void cpa_commit() { asm volatile("cp.async.commit_group;\n"); }
__device__ __forceinline__ void cpa_wait0()  { asm volatile("cp.async.wait_group 0;\n"); }

// packed fp32x2 FMA (Blackwell): d.xy += a.xy * b.xy  (two independent fp32 FMAs)
__device__ __forceinline__ unsigned long long pk2(float x, float y) {
    unsigned long long r;
    asm("mov.b64 %0, {%1, %2};" : "=l"(r) : "f"(x), "f"(y));
    return r;
}
__device__ __forceinline__ unsigned long long pk2dup(float x) {
    unsigned long long r;
    asm("mov.b64 %0, {%1, %1};" : "=l"(r) : "f"(x));
    return r;
}
__device__ __forceinline__ void fma2(unsigned long long& d, unsigned long long a, unsigned long long b) {
    asm("fma.rn.f32x2 %0, %1, %2, %0;" : "+l"(d) : "l"(a), "l"(b));
}
__device__ __forceinline__ void upk2(unsigned long long v, float& x, float& y) {
    asm("mov.b64 {%0, %1}, %2;" : "=f"(x), "=f"(y) : "l"(v));
}

// ---------------- kernel 1: row squared-norms ----------------
__global__ void __launch_bounds__(256)
rownorm_kernel(const float* __restrict__ A, int rows, float* __restrict__ outp) {
    int row = blockIdx.x * 8 + (threadIdx.x >> 5);
    int lane = threadIdx.x & 31;
    if (row >= rows) return;
    const float4* p = (const float4*)(A + (size_t)row * D_DIM);
    float s = 0.f;
#pragma unroll
    for (int i = 0; i < 2; i++) {
        float4 v = p[lane + 32 * i];
        s += v.x * v.x + v.y * v.y + v.z * v.z + v.w * v.w;
    }
#pragma unroll
    for (int o = 16; o; o >>= 1) s += __shfl_xor_sync(0xFFFFFFFFu, s, o);
    if (lane == 0) outp[row] = s;
}

// ---------------- kernel 2: fused NN-search (argmin over codes) + vq partials ----------------
__device__ __forceinline__ void load_tiles(const float* __restrict__ A, const float* __restrict__ B,
                                           int rowbase, int rowsTotal, int cb, int d0,
                                           uint32_t smA, uint32_t smB, int tid) {
#pragma unroll
    for (int it = 0; it < 4; it++) {
        int idx = tid + 256 * it;
        int row = idx >> 3, g = idx & 7;
        int ar = rowbase + row;
        int ok = (ar < rowsTotal);
        const float* src = A + (size_t)(ok ? ar : 0) * D_DIM + d0 + 4 * g;
        cpa16(smA + (row * ROWSTRIDE + 4 * g) * 4, src, ok ? 16 : 0);
    }
#pragma unroll
    for (int it = 0; it < 4; it++) {
        int idx = tid + 256 * it;
        int row = idx >> 3, g = idx & 7;
        const float* src = B + (size_t)(cb * TILE_K + row) * D_DIM + d0 + 4 * g;
        cpa16(smB + (row * ROWSTRIDE + 4 * g) * 4, src, 16);
    }
}

__global__ void __launch_bounds__(256)
argmin_kernel(const float* __restrict__ X, const float* __restrict__ C,
              const float* __restrict__ c2p, const float* __restrict__ x2p,
              float* __restrict__ partp, float* __restrict__ idxFp) {
    extern __shared__ float sm[];
    int tid = threadIdx.x;
    int tx = tid & 15, ty = tid >> 4;
    int rowbase = blockIdx.x * TILE_M;

    float* c2s = sm + 2 * STAGE_F;
    for (int i = tid; i < K_CODES; i += 256) c2s[i] = c2p[i];

    uint32_t smA0 = smem_u32(sm);
    uint32_t smB0 = smem_u32(sm + TILE_M * ROWSTRIDE);
    uint32_t smA1 = smem_u32(sm + STAGE_F);
    uint32_t smB1 = smem_u32(sm + STAGE_F + TILE_M * ROWSTRIDE);

    float bestv[8];
    int   besti[8];
#pragma unroll
    for (int i = 0; i < 8; i++) { bestv[i] = 3.0e38f; besti[i] = 0; }

    for (int kb = 0; kb < K_CODES / TILE_K; kb++) {
        __syncthreads();     // prior stage fully consumed

        // packed accumulators: acc2[i][m] = (dot[code tx+32m], dot[code tx+16+32m])
        unsigned long long acc2[8][4];
#pragma unroll
        for (int i = 0; i < 8; i++)
#pragma unroll
            for (int m = 0; m < 4; m++) acc2[i][m] = 0ULL;

        load_tiles(X, C, rowbase, N_ROWS, kb, 0, smA0, smB0, tid);
        cpa_commit();

        for (int t = 0; t < NDCHUNK; t++) {
            cpa_wait0();
            __syncthreads();
            if (t + 1 < NDCHUNK) {
                uint32_t dA = ((t + 1) & 1) ? smA1 : smA0;
                uint32_t dB = ((t + 1) & 1) ? smB1 : smB0;
                load_tiles(X, C, rowbase, N_ROWS, kb, (t + 1) * DCHUNK, dA, dB, tid);
                cpa_commit();
            }
            const float* As = sm + (t & 1) * STAGE_F;
            const float* Bs = As + TILE_M * ROWSTRIDE;
#pragma unroll 4
            for (int kk = 0; kk < DCHUNK; kk++) {
                float a[8], b[8];
#pragma unroll
                for (int i = 0; i < 8; i++) a[i] = As[(ty * 8 + i) * ROWSTRIDE + kk];
#pragma unroll
                for (int j = 0; j < 8; j++) b[j] = Bs[(tx + 16 * j) * ROWSTRIDE + kk];
                unsigned long long bb[4];
#pragma unroll
                for (int m = 0; m < 4; m++) bb[m] = pk2(b[2 * m], b[2 * m + 1]);
#pragma unroll
                for (int i = 0; i < 8; i++) {
                    unsigned long long aa = pk2dup(a[i]);
#pragma unroll
                    for (int m = 0; m < 4; m++) fma2(acc2[i][m], aa, bb[m]);
                }
            }
            __syncthreads();
        }

#pragma unroll
        for (int i = 0; i < 8; i++) {
#pragma unroll
            for (int m = 0; m < 4; m++) {
                float x, y;
                upk2(acc2[i][m], x, y);
                int c0 = kb * TILE_K + tx + 16 * (2 * m);
                int c1 = c0 + 16;
                float v0 = c2s[c0] - 2.0f * x;
                float v1 = c2s[c1] - 2.0f * y;
                if (v0 < bestv[i] || (v0 == bestv[i] && c0 < besti[i])) { bestv[i] = v0; besti[i] = c0; }
                if (v1 < bestv[i] || (v1 == bestv[i] && c1 < besti[i])) { bestv[i] = v1; besti[i] = c1; }
            }
        }
    }

    // cross-tx reduce via smem (reuse tile buffers)
    __syncthreads();
    float* red_v = sm;                       // [128][16]
    int*   red_i = (int*)(sm + 2048);        // [128][16]
    float* rowd  = sm + 4096;                // [128]
#pragma unroll
    for (int i = 0; i < 8; i++) {
        int r = ty * 8 + i;
        red_v[r * 16 + tx] = bestv[i];
        red_i[r * 16 + tx] = besti[i];
    }
    __syncthreads();
    if (tid < 128) {
        int r = tid;
        float bv = red_v[r * 16]; int bi = red_i[r * 16];
#pragma unroll
        for (int t = 1; t < 16; t++) {
            float v = red_v[r * 16 + t]; int ii = red_i[r * 16 + t];
            if (v < bv || (v == bv && ii < bi)) { bv = v; bi = ii; }
        }
        int rowg = rowbase + r;
        float d2 = 0.f;
        if (rowg < N_ROWS) {
            d2 = x2p[rowg] + bv;
            idxFp[rowg] = (float)bi;
        }
        rowd[r] = d2;
    }
    __syncthreads();
    for (int s = 64; s >= 1; s >>= 1) {
        if (tid < s && tid + s < 128) rowd[tid] += rowd[tid + s];
        __syncthreads();
    }
    if (tid == 0) partp[blockIdx.x] = rowd[0];
}

// ---------------- kernel 3: vq_loss finalize ----------------
__global__ void __launch_bounds__(256)
finalize_kernel(const float* __restrict__ partp, float* __restrict__ lossp, int writeLoss) {
    __shared__ float s[256];
    int tid = threadIdx.x;
    float v = 0.f;
    for (int i = tid; i < NTILES_N; i += 256) v += partp[i];
    s[tid] = v;
    __syncthreads();
    for (int o = 128; o >= 1; o >>= 1) {
        if (tid < o) s[tid] += s[tid + o];
        __syncthreads();
    }
    if (tid == 0 && writeLoss) {
        lossp[0] = 1.25f * s[0] / ((float)N_ROWS * (float)D_DIM);
    }
}

// ---------------- kernel 4: fused S-compute + gather ----------------
// Block b owns q-rows [16b, 16b+16). Computes S[16][1024] = Qrows @ C^T in smem,
// then writes score[q][n] = S[q - qb][idx[n]] for all n.
__global__ void __launch_bounds__(256)
fused_score_kernel(const float* __restrict__ Qm, const float* __restrict__ Cm,
                   const float* __restrict__ idxFp, float* __restrict__ outp) {
    extern __shared__ float sm[];
    int tid = threadIdx.x;
    int qb = blockIdx.x * FQ;

    // ---- load 16 query rows into smem (Aq[16][256]) ----
#pragma unroll
    for (int it = 0; it < 4; it++) {
        int id = tid + 256 * it;       // 0..1023
        int row = id >> 6;
        int c4 = id & 63;
        *(float4*)(sm + row * D_DIM + c4 * 4) =
            *(const float4*)(Qm + (size_t)(qb + row) * D_DIM + c4 * 4);
    }

    int qg = tid >> 7;     // 0..1  (8-row group)
    int cg = tid & 127;    // 0..127 (8-code group)
    int sw = cg & 3;       // bank swizzle key

    float acc[8][8];
#pragma unroll
    for (int i = 0; i < 8; i++)
#pragma unroll
        for (int j = 0; j < 8; j++) acc[i][j] = 0.f;

    uint32_t bbase = smem_u32(sm + FS_AQ_F);

    for (int dc = 0; dc < D_DIM / 16; dc++) {   // 16 chunks of 16 d
        __syncthreads();   // prior chunk consumed (and Aq ready on first iter)
        // stage codebook chunk: Bbuf[1024 codes][16 d] (padded row = 20 floats, xor-swizzled)
#pragma unroll
        for (int it = 0; it < 16; it++) {
            int id = tid + 256 * it;   // 0..4095
            int code = id >> 2;
            int dg = id & 3;
            int dsw = dg ^ ((code >> 3) & 3);
            cpa16(bbase + (uint32_t)(code * FS_BROW + dsw * 4) * 4,
                  Cm + (size_t)code * D_DIM + dc * 16 + dg * 4, 16);
        }
        cpa_commit();
        cpa_wait0();
        __syncthreads();

        const float* Bb = sm + FS_AQ_F;
#pragma unroll
        for (int kk4 = 0; kk4 < 4; kk4++) {
            int ks = (kk4 ^ sw) << 2;
            float4 b4[8];
#pragma unroll
            for (int j = 0; j < 8; j++)
                b4[j] = *(const float4*)(Bb + (cg * 8 + j) * FS_BROW + ks);
#pragma unroll
            for (int i = 0; i < 8; i++) {
                float4 a4 = *(const float4*)(sm + (qg * 8 + i) * D_DIM + dc * 16 + kk4 * 4);
#pragma unroll
                for (int j = 0; j < 8; j++) {
                    acc[i][j] = fmaf(a4.x, b4[j].x, acc[i][j]);
                    acc[i][j] = fmaf(a4.y, b4[j].y, acc[i][j]);
                    acc[i][j] = fmaf(a4.z, b4[j].z, acc[i][j]);
                    acc[i][j] = fmaf(a4.w, b4[j].w, acc[i][j]);
                }
            }
        }
    }

    __syncthreads();   // all Bbuf reads done before S overlays it
    float* S = sm + FS_AQ_F;     // S[16][1024] overlays Bbuf
#pragma unroll
    for (int i = 0; i < 8; i++) {
#pragma unroll
        for (int j4 = 0; j4 < 2; j4++) {
            float4 v = make_float4(acc[i][j4 * 4 + 0], acc[i][j4 * 4 + 1],
                                   acc[i][j4 * 4 + 2], acc[i][j4 * 4 + 3]);
            *(float4*)(S + (qg * 8 + i) * K_CODES + cg * 8 + j4 * 4) = v;
        }
    }
    __syncthreads();

    // ---- gather phase: score[qb+q][n] = S[q][idx[n]] ----
    for (int base = 0; base < N_ROWS; base += 1024) {
        int n = base + (tid << 2);
        if (n < N_ROWS) {          // N_ROWS % 4 == 0 -> whole float4 valid
            int i0 = (int)(idxFp[n + 0] + 0.5f);
            int i1 = (int)(idxFp[n + 1] + 0.5f);
            int i2 = (int)(idxFp[n + 2] + 0.5f);
            int i3 = (int)(idxFp[n + 3] + 0.5f);
#pragma unroll
            for (int q = 0; q < FQ; q++) {
                const float* Sr = S + q * K_CODES;
                float4 v = make_float4(Sr[i0], Sr[i1], Sr[i2], Sr[i3]);
                *(float4*)(outp + (size_t)(qb + q) * N_ROWS + n) = v;
            }
        }
    }
}

// ---------------- host launch ----------------
extern "C" void kernel_launch(void* const* d_in, const int* in_sizes, int n_in,
                              void* d_out, int out_size) {
    const float* Qm = nullptr;
    const float* Xm = nullptr;
    const float* Cm = nullptr;
    for (int i = 0; i < n_in; i++) {
        if (in_sizes[i] == Q_ROWS * D_DIM)       Qm = (const float*)d_in[i];
        else if (in_sizes[i] == N_ROWS * D_DIM)  Xm = (const float*)d_in[i];
        else if (in_sizes[i] == K_CODES * D_DIM) Cm = (const float*)d_in[i];
    }
    if (!Qm && n_in > 0) Qm = (const float*)d_in[0];
    if (!Xm && n_in > 1) Xm = (const float*)d_in[1];
    if (!Cm && n_in > 2) Cm = (const float*)d_in[2];

    float* out = (float*)d_out;
    bool hasExtra = ((size_t)out_size >= QN + 1 + N_ROWS);

    // Scratch carved out of the score region (overwritten last by fused_score):
    float* c2p   = out;            // [0, 1024)
    float* partp = out + 1024;     // [1024, 1415)
    float* x2p   = out + 2048;     // [2048, 52048)
    float* idxp  = hasExtra ? (out + QN + 1) : (out + (QN - N_ROWS));
    float* lossp = out + QN;       // only written when hasExtra

    (void)cudaFuncSetAttribute(argmin_kernel,      cudaFuncAttributeMaxDynamicSharedMemorySize, GEMM_SMEM_B);
    (void)cudaFuncSetAttribute(fused_score_kernel, cudaFuncAttributeMaxDynamicSharedMemorySize, FS_SMEM_B);

    // 1. norms (stream-ordered producers of c2/x2 scratch)
    rownorm_kernel<<<(K_CODES + 7) / 8, 256>>>(Cm, K_CODES, c2p);
    rownorm_kernel<<<(N_ROWS + 7) / 8, 256>>>(Xm, N_ROWS, x2p);

    // 2. nearest-neighbor argmin + vq partials (writes idx to its output slot)
    argmin_kernel<<<NTILES_N, 256, GEMM_SMEM_B>>>(Xm, Cm, c2p, x2p, partp, idxp);

    // 3. vq_loss
    finalize_kernel<<<1, 256>>>(partp, lossp, hasExtra ? 1 : 0);

    // 4. fused S = Q@C^T (per-block, in smem) + score gather (overwrites all scratch)
    fused_score_kernel<<<Q_ROWS / FQ, 256, FS_SMEM_B>>>(Qm, Cm, idxp, out);
}

// round 13
// speedup vs baseline: 2.3867x; 2.3867x over previous
#include <cuda_runtime.h>
#include <cuda_bf16.h>
#include <cstdint>
#include <cstddef>

// ---------------- problem constants ----------------
#define Q_ROWS  4096
#define N_ROWS  50000
#define K_CODES 1024
#define D_DIM   256
#define NTILES_N 391                 // ceil(50000/128)
#define QN ((size_t)Q_ROWS * N_ROWS)
#define NFIX_BLOCKS 6250             // ceil(50000/8) fixup blocks

// ---------------- bf16 split-K ----------------
#define K_EXT   768                  // [hi|hi|lo] x [hi|lo|hi]
#define XE_ROWS 50048                // 391*128
#define ROWB    (K_EXT * 2)          // 1536 bytes per row

// scratch float-offsets inside d_out (overwritten last by fused_score)
#define XE_OFF_F    65536            // Xe bf16 [50048][768]
#define CE_OFF_F    19400704         // Ce bf16 [1024][768] (ends 19793920)
#define CAND0_OFF_F 19793920         // top-1 candidate idx per row
#define CAND1_OFF_F 19844096         // top-2 candidate idx per row
#define PART_OFF_F  19894272         // fixup partials [6250]

// ---------------- argmin mma smem (bytes) ----------------
#define AM_C2   0
#define AM_A0   4096
#define AM_B0   20480
#define AM_A1   36864
#define AM_B1   53248
#define AM_SMEM_B 69632

// ---------------- fused S+gather tiling (proven in R9) ----------------
#define FQ 16
#define FS_AQ_F   (FQ * D_DIM)
#define FS_BROW   20
#define FS_BBUF_F (K_CODES * FS_BROW)
#define FS_SMEM_F (FS_AQ_F + FS_BBUF_F)
#define FS_SMEM_B (FS_SMEM_F * 4)      // 98304 B

// ---------------- helpers ----------------
__device__ __forceinline__ uint32_t smem_u32(const void* p) {
    uint32_t a;
    asm("{ .reg .u64 t; cvta.to.shared.u64 t, %1; cvt.u32.u64 %0, t; }" : "=r"(a) : "l"(p));
    return a;
}
__device__ __forceinline__ void cpa16(uint32_t dst, const void* src) {
    asm volatile("cp.async.cg.shared.global [%0], [%1], 16;\n" :: "r"(dst), "l"(src));
}
__device__ __forceinline__ void cpa_commit() { asm volatile("cp.async.commit_group;\n"); }
__device__ __forceinline__ void cpa_wait0()  { asm volatile("cp.async.wait_group 0;\n"); }

#define SWZ128(off) ((off) ^ (((off) >> 3) & 0x70))

#define LDSM4(r0, r1, r2, r3, addr) \
    asm volatile("ldmatrix.sync.aligned.m8n8.x4.shared.b16 {%0,%1,%2,%3}, [%4];" \
                 : "=r"(r0), "=r"(r1), "=r"(r2), "=r"(r3) : "r"(addr))

#define MMA16816(c, a0, a1, a2, a3, b0, b1) \
    asm volatile("mma.sync.aligned.m16n8k16.row.col.f32.bf16.bf16.f32 " \
                 "{%0,%1,%2,%3}, {%4,%5,%6,%7}, {%8,%9}, {%0,%1,%2,%3};" \
                 : "+f"((c)[0]), "+f"((c)[1]), "+f"((c)[2]), "+f"((c)[3]) \
                 : "r"(a0), "r"(a1), "r"(a2), "r"(a3), "r"(b0), "r"(b1))

// top-2 update: (bv,bi) best, (sv,si) runner-up
__device__ __forceinline__ void top2_update(float v, int c, float& bv, int& bi, float& sv, int& si) {
    if (v < bv) { sv = bv; si = bi; bv = v; bi = c; }
    else if (v < sv) { sv = v; si = c; }
}
__device__ __forceinline__ void top2_merge(float obv, int obi, float osv, int osi,
                                           float& bv, int& bi, float& sv, int& si) {
    if (obv < bv) {
        float nsv = (bv < osv) ? bv : osv;
        int   nsi = (bv < osv) ? bi : osi;
        bv = obv; bi = obi; sv = nsv; si = nsi;
    } else if (obv < sv) {
        sv = obv; si = obi;
    }
}

// ---------------- kernel 1: row squared-norms ----------------
__global__ void __launch_bounds__(256)
rownorm_kernel(const float* __restrict__ A, int rows, float* __restrict__ outp) {
    int row = blockIdx.x * 8 + (threadIdx.x >> 5);
    int lane = threadIdx.x & 31;
    if (row >= rows) return;
    const float4* p = (const float4*)(A + (size_t)row * D_DIM);
    float s = 0.f;
#pragma unroll
    for (int i = 0; i < 2; i++) {
        float4 v = p[lane + 32 * i];
        s += v.x * v.x + v.y * v.y + v.z * v.z + v.w * v.w;
    }
#pragma unroll
    for (int o = 16; o; o >>= 1) s += __shfl_xor_sync(0xFFFFFFFFu, s, o);
    if (lane == 0) outp[row] = s;
}

// ---------------- kernel 2: fp32 -> bf16 hi/lo split, K-folded layout ----------------
__global__ void __launch_bounds__(256)
convert_kernel(const float* __restrict__ src, unsigned short* __restrict__ dst,
               int rowsValid, int rowsTotal, int dupHiOff, int loOff) {
    long long id = (long long)blockIdx.x * 256 + threadIdx.x;   // one per 8 floats
    int row = (int)(id >> 5);
    int seg = (int)(id & 31);
    if (row >= rowsTotal) return;
    float v[8];
    if (row < rowsValid) {
        const float4* p = (const float4*)(src + (size_t)row * D_DIM + seg * 8);
        float4 a = p[0], b = p[1];
        v[0] = a.x; v[1] = a.y; v[2] = a.z; v[3] = a.w;
        v[4] = b.x; v[5] = b.y; v[6] = b.z; v[7] = b.w;
    } else {
#pragma unroll
        for (int i = 0; i < 8; i++) v[i] = 0.f;
    }
    uint32_t hu[4], lu[4];
#pragma unroll
    for (int i = 0; i < 4; i++) {
        __nv_bfloat16 h0 = __float2bfloat16(v[2 * i]);
        __nv_bfloat16 h1 = __float2bfloat16(v[2 * i + 1]);
        __nv_bfloat16 l0 = __float2bfloat16(v[2 * i] - __bfloat162float(h0));
        __nv_bfloat16 l1 = __float2bfloat16(v[2 * i + 1] - __bfloat162float(h1));
        unsigned short h0u = *(unsigned short*)&h0, h1u = *(unsigned short*)&h1;
        unsigned short l0u = *(unsigned short*)&l0, l1u = *(unsigned short*)&l1;
        hu[i] = (uint32_t)h0u | ((uint32_t)h1u << 16);
        lu[i] = (uint32_t)l0u | ((uint32_t)l1u << 16);
    }
    uint4 hq = make_uint4(hu[0], hu[1], hu[2], hu[3]);
    uint4 lq = make_uint4(lu[0], lu[1], lu[2], lu[3]);
    size_t rb = (size_t)row * K_EXT;
    *(uint4*)(dst + rb + seg * 8)            = hq;
    *(uint4*)(dst + rb + dupHiOff + seg * 8) = hq;
    *(uint4*)(dst + rb + loOff + seg * 8)    = lq;
}

// ---------------- kernel 3: mma.sync bf16 top-2 candidate search ----------------
__device__ __forceinline__ void am_load_stage(uint32_t smA, uint32_t smB,
                                              const char* XeB, const char* CeB,
                                              int rowbase, int cc, int kc, int tid) {
#pragma unroll
    for (int it = 0; it < 4; it++) {
        int idx = tid + 256 * it;
        int row = idx >> 3, seg = idx & 7;
        uint32_t off = (uint32_t)(row * 128 + seg * 16);
        cpa16(smA + SWZ128(off), XeB + (size_t)(rowbase + row) * ROWB + kc * 128 + seg * 16);
    }
#pragma unroll
    for (int it = 0; it < 4; it++) {
        int idx = tid + 256 * it;
        int row = idx >> 3, seg = idx & 7;
        uint32_t off = (uint32_t)(row * 128 + seg * 16);
        cpa16(smB + SWZ128(off), CeB + (size_t)(cc * 128 + row) * ROWB + kc * 128 + seg * 16);
    }
}

__global__ void __launch_bounds__(256)
argmin_mma_kernel(const unsigned short* __restrict__ Xe, const unsigned short* __restrict__ Ce,
                  const float* __restrict__ c2p,
                  float* __restrict__ cand0p, float* __restrict__ cand1p) {
    extern __shared__ char smc[];
    uint32_t sbase = smem_u32(smc);
    int tid = threadIdx.x;
    int lane = tid & 31, w = tid >> 5;
    int rowbase = blockIdx.x * 128;

    float* c2s = (float*)(smc + AM_C2);
    for (int i = tid; i < K_CODES; i += 256) c2s[i] = c2p[i];

    const char* XeB = (const char*)Xe;
    const char* CeB = (const char*)Ce;
    uint32_t smA[2] = { sbase + AM_A0, sbase + AM_A1 };
    uint32_t smB[2] = { sbase + AM_B0, sbase + AM_B1 };

    int g = lane >> 3;
    int arow = 16 * w + ((g & 1) ? 8 : 0) + (lane & 7);
    uint32_t akoff = (g >= 2) ? 16u : 0u;
    uint32_t amask = (uint32_t)((arow & 7) * 16);
    int brow_base = ((g >= 2) ? 8 : 0) + (lane & 7);
    uint32_t bkoff = (uint32_t)((g & 1) * 16);

    float bv0 = 3.0e38f, sv0 = 3.0e38f, bv1 = 3.0e38f, sv1 = 3.0e38f;
    int   bi0 = 0, si0 = 0, bi1 = 0, si1 = 0;

    for (int cc = 0; cc < 8; cc++) {
        float acc[16][4];
#pragma unroll
        for (int j = 0; j < 16; j++)
#pragma unroll
            for (int r = 0; r < 4; r++) acc[j][r] = 0.f;

        __syncthreads();
        am_load_stage(smA[0], smB[0], XeB, CeB, rowbase, cc, 0, tid);
        cpa_commit();

        for (int kc = 0; kc < 12; kc++) {
            cpa_wait0();
            __syncthreads();
            if (kc + 1 < 12) {
                am_load_stage(smA[(kc + 1) & 1], smB[(kc + 1) & 1], XeB, CeB, rowbase, cc, kc + 1, tid);
                cpa_commit();
            }
            uint32_t aT = smA[kc & 1], bT = smB[kc & 1];
#pragma unroll
            for (int ks = 0; ks < 4; ks++) {
                uint32_t a0, a1, a2, a3;
                uint32_t aaddr = aT + (uint32_t)(arow * 128) + (((uint32_t)(ks * 32) + akoff) ^ amask);
                LDSM4(a0, a1, a2, a3, aaddr);
#pragma unroll
                for (int t = 0; t < 8; t++) {
                    int brow = 16 * t + brow_base;
                    uint32_t bmask = (uint32_t)((brow & 7) * 16);
                    uint32_t baddr = bT + (uint32_t)(brow * 128) + (((uint32_t)(ks * 32) + bkoff) ^ bmask);
                    uint32_t b0, b1, b2, b3;
                    LDSM4(b0, b1, b2, b3, baddr);
                    MMA16816(acc[2 * t],     a0, a1, a2, a3, b0, b1);
                    MMA16816(acc[2 * t + 1], a0, a1, a2, a3, b2, b3);
                }
            }
            __syncthreads();
        }

        // epilogue: v = c2[code] - 2*dot; top-2 update per owned row
        int colb = 2 * (lane & 3);
#pragma unroll
        for (int j = 0; j < 16; j++) {
            int code = cc * 128 + 8 * j + colb;
            float c2a = c2s[code], c2b = c2s[code + 1];
            top2_update(c2a - 2.0f * acc[j][0], code,     bv0, bi0, sv0, si0);
            top2_update(c2b - 2.0f * acc[j][1], code + 1, bv0, bi0, sv0, si0);
            top2_update(c2a - 2.0f * acc[j][2], code,     bv1, bi1, sv1, si1);
            top2_update(c2b - 2.0f * acc[j][3], code + 1, bv1, bi1, sv1, si1);
        }
    }

    // quad reduce top-2 (lanes sharing lane>>2 hold the same two rows)
#pragma unroll
    for (int off = 1; off <= 2; off <<= 1) {
        float obv0 = __shfl_xor_sync(0xFFFFFFFFu, bv0, off);
        int   obi0 = __shfl_xor_sync(0xFFFFFFFFu, bi0, off);
        float osv0 = __shfl_xor_sync(0xFFFFFFFFu, sv0, off);
        int   osi0 = __shfl_xor_sync(0xFFFFFFFFu, si0, off);
        float obv1 = __shfl_xor_sync(0xFFFFFFFFu, bv1, off);
        int   obi1 = __shfl_xor_sync(0xFFFFFFFFu, bi1, off);
        float osv1 = __shfl_xor_sync(0xFFFFFFFFu, sv1, off);
        int   osi1 = __shfl_xor_sync(0xFFFFFFFFu, si1, off);
        top2_merge(obv0, obi0, osv0, osi0, bv0, bi0, sv0, si0);
        top2_merge(obv1, obi1, osv1, osi1, bv1, bi1, sv1, si1);
    }

    int r0g = rowbase + 16 * w + (lane >> 2);
    int r1g = r0g + 8;
    if ((lane & 3) == 0) {
        cand0p[r0g] = (float)bi0; cand1p[r0g] = (float)si0;
        cand0p[r1g] = (float)bi1; cand1p[r1g] = (float)si1;
    }
}

// ---------------- kernel 4: exact fp32 fixup of top-2 candidates + vq partials ----------------
__global__ void __launch_bounds__(256)
fixup_kernel(const float* __restrict__ X, const float* __restrict__ C,
             const float* __restrict__ c2p, const float* __restrict__ x2p,
             const float* __restrict__ cand0p, const float* __restrict__ cand1p,
             float* __restrict__ partp, float* __restrict__ idxFp) {
    __shared__ float wsum[8];
    int lane = threadIdx.x & 31, w = threadIdx.x >> 5;
    int row = blockIdx.x * 8 + w;
    float contrib = 0.f;
    if (row < N_ROWS) {
        int c0 = (int)(cand0p[row] + 0.5f);
        int c1 = (int)(cand1p[row] + 0.5f);
        const float4* xr = (const float4*)(X + (size_t)row * D_DIM);
        const float4* a0 = (const float4*)(C + (size_t)c0 * D_DIM);
        const float4* a1 = (const float4*)(C + (size_t)c1 * D_DIM);
        float d0 = 0.f, d1 = 0.f;
#pragma unroll
        for (int i = 0; i < 2; i++) {
            float4 xv = xr[lane + 32 * i];
            float4 v0 = a0[lane + 32 * i];
            float4 v1 = a1[lane + 32 * i];
            d0 += xv.x * v0.x + xv.y * v0.y + xv.z * v0.z + xv.w * v0.w;
            d1 += xv.x * v1.x + xv.y * v1.y + xv.z * v1.z + xv.w * v1.w;
        }
#pragma unroll
        for (int o = 16; o; o >>= 1) {
            d0 += __shfl_xor_sync(0xFFFFFFFFu, d0, o);
            d1 += __shfl_xor_sync(0xFFFFFFFFu, d1, o);
        }
        float v0 = c2p[c0] - 2.0f * d0;
        float v1 = c2p[c1] - 2.0f * d1;
        int   bi = (v1 < v0 || (v1 == v0 && c1 < c0)) ? c1 : c0;
        float bv = (v1 < v0 || (v1 == v0 && c1 < c0)) ? v1 : v0;
        if (lane == 0) {
            idxFp[row] = (float)bi;
            contrib = x2p[row] + bv;
        }
    }
    if (lane == 0) wsum[w] = contrib;
    __syncthreads();
    if (threadIdx.x == 0) {
        float s = 0.f;
#pragma unroll
        for (int i = 0; i < 8; i++) s += wsum[i];
        partp[blockIdx.x] = s;
    }
}

// ---------------- kernel 5: vq_loss finalize ----------------
__global__ void __launch_bounds__(256)
finalize_kernel(const float* __restrict__ partp, float* __restrict__ lossp, int writeLoss) {
    __shared__ float s[256];
    int tid = threadIdx.x;
    float v = 0.f;
    for (int i = tid; i < NFIX_BLOCKS; i += 256) v += partp[i];
    s[tid] = v;
    __syncthreads();
    for (int o = 128; o >= 1; o >>= 1) {
        if (tid < o) s[tid] += s[tid + o];
        __syncthreads();
    }
    if (tid == 0 && writeLoss) {
        lossp[0] = 1.25f * s[0] / ((float)N_ROWS * (float)D_DIM);
    }
}

// ---------------- kernel 6: fused S-compute + gather (unchanged from R9) ----------------
__global__ void __launch_bounds__(256)
fused_score_kernel(const float* __restrict__ Qm, const float* __restrict__ Cm,
                   const float* __restrict__ idxFp, float* __restrict__ outp) {
    extern __shared__ float sm[];
    int tid = threadIdx.x;
    int qb = blockIdx.x * FQ;

#pragma unroll
    for (int it = 0; it < 4; it++) {
        int id = tid + 256 * it;
        int row = id >> 6;
        int c4 = id & 63;
        *(float4*)(sm + row * D_DIM + c4 * 4) =
            *(const float4*)(Qm + (size_t)(qb + row) * D_DIM + c4 * 4);
    }

    int qg = tid >> 7;
    int cg = tid & 127;
    int sw = cg & 3;

    float acc[8][8];
#pragma unroll
    for (int i = 0; i < 8; i++)
#pragma unroll
        for (int j = 0; j < 8; j++) acc[i][j] = 0.f;

    uint32_t bbase = smem_u32(sm + FS_AQ_F);

    for (int dc = 0; dc < D_DIM / 16; dc++) {
        __syncthreads();
#pragma unroll
        for (int it = 0; it < 16; it++) {
            int id = tid + 256 * it;
            int code = id >> 2;
            int dg = id & 3;
            int dsw = dg ^ ((code >> 3) & 3);
            cpa16(bbase + (uint32_t)(code * FS_BROW + dsw * 4) * 4,
                  Cm + (size_t)code * D_DIM + dc * 16 + dg * 4);
        }
        cpa_commit();
        cpa_wait0();
        __syncthreads();

        const float* Bb = sm + FS_AQ_F;
#pragma unroll
        for (int kk4 = 0; kk4 < 4; kk4++) {
            int ks = (kk4 ^ sw) << 2;
            float4 b4[8];
#pragma unroll
            for (int j = 0; j < 8; j++)
                b4[j] = *(const float4*)(Bb + (cg * 8 + j) * FS_BROW + ks);
#pragma unroll
            for (int i = 0; i < 8; i++) {
                float4 a4 = *(const float4*)(sm + (qg * 8 + i) * D_DIM + dc * 16 + kk4 * 4);
#pragma unroll
                for (int j = 0; j < 8; j++) {
                    acc[i][j] = fmaf(a4.x, b4[j].x, acc[i][j]);
                    acc[i][j] = fmaf(a4.y, b4[j].y, acc[i][j]);
                    acc[i][j] = fmaf(a4.z, b4[j].z, acc[i][j]);
                    acc[i][j] = fmaf(a4.w, b4[j].w, acc[i][j]);
                }
            }
        }
    }

    __syncthreads();
    float* S = sm + FS_AQ_F;
#pragma unroll
    for (int i = 0; i < 8; i++) {
#pragma unroll
        for (int j4 = 0; j4 < 2; j4++) {
            float4 v = make_float4(acc[i][j4 * 4 + 0], acc[i][j4 * 4 + 1],
                                   acc[i][j4 * 4 + 2], acc[i][j4 * 4 + 3]);
            *(float4*)(S + (qg * 8 + i) * K_CODES + cg * 8 + j4 * 4) = v;
        }
    }
    __syncthreads();

    for (int base = 0; base < N_ROWS; base += 1024) {
        int n = base + (tid << 2);
        if (n < N_ROWS) {
            int i0 = (int)(idxFp[n + 0] + 0.5f);
            int i1 = (int)(idxFp[n + 1] + 0.5f);
            int i2 = (int)(idxFp[n + 2] + 0.5f);
            int i3 = (int)(idxFp[n + 3] + 0.5f);
#pragma unroll
            for (int q = 0; q < FQ; q++) {
                const float* Sr = S + q * K_CODES;
                float4 v = make_float4(Sr[i0], Sr[i1], Sr[i2], Sr[i3]);
                *(float4*)(outp + (size_t)(qb + q) * N_ROWS + n) = v;
            }
        }
    }
}

// ---------------- host launch ----------------
extern "C" void kernel_launch(void* const* d_in, const int* in_sizes, int n_in,
                              void* d_out, int out_size) {
    const float* Qm = nullptr;
    const float* Xm = nullptr;
    const float* Cm = nullptr;
    for (int i = 0; i < n_in; i++) {
        if (in_sizes[i] == Q_ROWS * D_DIM)       Qm = (const float*)d_in[i];
        else if (in_sizes[i] == N_ROWS * D_DIM)  Xm = (const float*)d_in[i];
        else if (in_sizes[i] == K_CODES * D_DIM) Cm = (const float*)d_in[i];
    }
    if (!Qm && n_in > 0) Qm = (const float*)d_in[0];
    if (!Xm && n_in > 1) Xm = (const float*)d_in[1];
    if (!Cm && n_in > 2) Cm = (const float*)d_in[2];

    float* out = (float*)d_out;
    bool hasExtra = ((size_t)out_size >= QN + 1 + N_ROWS);

    // Scratch carved from the score region (overwritten last by fused_score):
    float* c2p    = out;                  // [0, 1024)
    float* x2p    = out + 2048;           // [2048, 52048)
    unsigned short* Xe = (unsigned short*)(out + XE_OFF_F);
    unsigned short* Ce = (unsigned short*)(out + CE_OFF_F);
    float* cand0p = out + CAND0_OFF_F;
    float* cand1p = out + CAND1_OFF_F;
    float* partp  = out + PART_OFF_F;
    float* idxp   = hasExtra ? (out + QN + 1) : (out + (QN - N_ROWS));
    float* lossp  = out + QN;

    (void)cudaFuncSetAttribute(argmin_mma_kernel,  cudaFuncAttributeMaxDynamicSharedMemorySize, AM_SMEM_B);
    (void)cudaFuncSetAttribute(fused_score_kernel, cudaFuncAttributeMaxDynamicSharedMemorySize, FS_SMEM_B);

    // 1. norms
    rownorm_kernel<<<(K_CODES + 7) / 8, 256>>>(Cm, K_CODES, c2p);
    rownorm_kernel<<<(N_ROWS + 7) / 8, 256>>>(Xm, N_ROWS, x2p);

    // 2. bf16 hi/lo split conversions: X -> [hi|hi|lo], C -> [hi|lo|hi]
    convert_kernel<<<(XE_ROWS * 32 + 255) / 256, 256>>>(Xm, Xe, N_ROWS, XE_ROWS, 256, 512);
    convert_kernel<<<(K_CODES * 32 + 255) / 256, 256>>>(Cm, Ce, K_CODES, K_CODES, 512, 256);

    // 3. mma.sync top-2 candidate search
    argmin_mma_kernel<<<NTILES_N, 256, AM_SMEM_B>>>(Xe, Ce, c2p, cand0p, cand1p);

    // 4. exact fp32 fixup -> nearest_idx + vq partials
    fixup_kernel<<<NFIX_BLOCKS, 256>>>(Xm, Cm, c2p, x2p, cand0p, cand1p, partp, idxp);

    // 5. vq_loss
    finalize_kernel<<<1, 256>>>(partp, lossp, hasExtra ? 1 : 0);

    // 6. fused S = Q@C^T + score gather (overwrites all scratch)
    fused_score_kernel<<<Q_ROWS / FQ, 256, FS_SMEM_B>>>(Qm, Cm, idxp, out);
}

// round 14
// speedup vs baseline: 2.4028x; 1.0067x over previous
#include <cuda_runtime.h>
#include <cuda_bf16.h>
#include <cstdint>
#include <cstddef>

// ---------------- problem constants ----------------
#define Q_ROWS  4096
#define N_ROWS  50000
#define K_CODES 1024
#define D_DIM   256
#define NTILES_N 391                 // ceil(50000/128)
#define QN ((size_t)Q_ROWS * N_ROWS)
#define NFIX_BLOCKS 6250             // ceil(50000/8) fixup blocks

// ---------------- bf16 split-K ----------------
#define K_EXT   768                  // [hi|hi|lo] x [hi|lo|hi]
#define XE_ROWS 50048                // 391*128
#define ROWB    (K_EXT * 2)          // 1536 bytes per row

// scratch float-offsets inside d_out (overwritten last by fused_score)
#define XE_OFF_F    65536            // Xe bf16 [50048][768]
#define CE_OFF_F    19400704         // Ce bf16 [1024][768] (ends 19793920)
#define CAND0_OFF_F 19793920         // top-1 candidate idx per row
#define CAND1_OFF_F 19844096         // top-2 candidate idx per row
#define PART_OFF_F  19894272         // fixup partials [6250]

// ---------------- argmin mma smem (bytes) ----------------
#define AM_C2   0
#define AM_A0   4096
#define AM_B0   20480
#define AM_A1   36864
#define AM_B1   53248
#define AM_SMEM_B 69632

// ---------------- fused S+gather tiling (proven in R9) ----------------
#define FQ 16
#define FS_AQ_F   (FQ * D_DIM)
#define FS_BROW   20
#define FS_BBUF_F (K_CODES * FS_BROW)
#define FS_SMEM_F (FS_AQ_F + FS_BBUF_F)
#define FS_SMEM_B (FS_SMEM_F * 4)      // 98304 B

// ---------------- helpers ----------------
__device__ __forceinline__ uint32_t smem_u32(const void* p) {
    uint32_t a;
    asm("{ .reg .u64 t; cvta.to.shared.u64 t, %1; cvt.u32.u64 %0, t; }" : "=r"(a) : "l"(p));
    return a;
}
__device__ __forceinline__ void cpa16(uint32_t dst, const void* src) {
    asm volatile("cp.async.cg.shared.global [%0], [%1], 16;\n" :: "r"(dst), "l"(src));
}
__device__ __forceinline__ void cpa_commit() { asm volatile("cp.async.commit_group;\n"); }
__device__ __forceinline__ void cpa_wait0()  { asm volatile("cp.async.wait_group 0;\n"); }

#define SWZ128(off) ((off) ^ (((off) >> 3) & 0x70))

#define LDSM4(r0, r1, r2, r3, addr) \
    asm volatile("ldmatrix.sync.aligned.m8n8.x4.shared.b16 {%0,%1,%2,%3}, [%4];" \
                 : "=r"(r0), "=r"(r1), "=r"(r2), "=r"(r3) : "r"(addr))

#define MMA16816(c, a0, a1, a2, a3, b0, b1) \
    asm volatile("mma.sync.aligned.m16n8k16.row.col.f32.bf16.bf16.f32 " \
                 "{%0,%1,%2,%3}, {%4,%5,%6,%7}, {%8,%9}, {%0,%1,%2,%3};" \
                 : "+f"((c)[0]), "+f"((c)[1]), "+f"((c)[2]), "+f"((c)[3]) \
                 : "r"(a0), "r"(a1), "r"(a2), "r"(a3), "r"(b0), "r"(b1))

// top-2 update: (bv,bi) best, (sv,si) runner-up
__device__ __forceinline__ void top2_update(float v, int c, float& bv, int& bi, float& sv, int& si) {
    if (v < bv) { sv = bv; si = bi; bv = v; bi = c; }
    else if (v < sv) { sv = v; si = c; }
}
__device__ __forceinline__ void top2_merge(float obv, int obi, float osv, int osi,
                                           float& bv, int& bi, float& sv, int& si) {
    if (obv < bv) {
        float nsv = (bv < osv) ? bv : osv;
        int   nsi = (bv < osv) ? bi : osi;
        bv = obv; bi = obi; sv = nsv; si = nsi;
    } else if (obv < sv) {
        sv = obv; si = obi;
    }
}

// ---------------- kernel 1: row squared-norms ----------------
__global__ void __launch_bounds__(256)
rownorm_kernel(const float* __restrict__ A, int rows, float* __restrict__ outp) {
    int row = blockIdx.x * 8 + (threadIdx.x >> 5);
    int lane = threadIdx.x & 31;
    if (row >= rows) return;
    const float4* p = (const float4*)(A + (size_t)row * D_DIM);
    float s = 0.f;
#pragma unroll
    for (int i = 0; i < 2; i++) {
        float4 v = p[lane + 32 * i];
        s += v.x * v.x + v.y * v.y + v.z * v.z + v.w * v.w;
    }
#pragma unroll
    for (int o = 16; o; o >>= 1) s += __shfl_xor_sync(0xFFFFFFFFu, s, o);
    if (lane == 0) outp[row] = s;
}

// ---------------- kernel 2: fp32 -> bf16 hi/lo split, K-folded layout ----------------
__global__ void __launch_bounds__(256)
convert_kernel(const float* __restrict__ src, unsigned short* __restrict__ dst,
               int rowsValid, int rowsTotal, int dupHiOff, int loOff) {
    long long id = (long long)blockIdx.x * 256 + threadIdx.x;   // one per 8 floats
    int row = (int)(id >> 5);
    int seg = (int)(id & 31);
    if (row >= rowsTotal) return;
    float v[8];
    if (row < rowsValid) {
        const float4* p = (const float4*)(src + (size_t)row * D_DIM + seg * 8);
        float4 a = p[0], b = p[1];
        v[0] = a.x; v[1] = a.y; v[2] = a.z; v[3] = a.w;
        v[4] = b.x; v[5] = b.y; v[6] = b.z; v[7] = b.w;
    } else {
#pragma unroll
        for (int i = 0; i < 8; i++) v[i] = 0.f;
    }
    uint32_t hu[4], lu[4];
#pragma unroll
    for (int i = 0; i < 4; i++) {
        __nv_bfloat16 h0 = __float2bfloat16(v[2 * i]);
        __nv_bfloat16 h1 = __float2bfloat16(v[2 * i + 1]);
        __nv_bfloat16 l0 = __float2bfloat16(v[2 * i] - __bfloat162float(h0));
        __nv_bfloat16 l1 = __float2bfloat16(v[2 * i + 1] - __bfloat162float(h1));
        unsigned short h0u = *(unsigned short*)&h0, h1u = *(unsigned short*)&h1;
        unsigned short l0u = *(unsigned short*)&l0, l1u = *(unsigned short*)&l1;
        hu[i] = (uint32_t)h0u | ((uint32_t)h1u << 16);
        lu[i] = (uint32_t)l0u | ((uint32_t)l1u << 16);
    }
    uint4 hq = make_uint4(hu[0], hu[1], hu[2], hu[3]);
    uint4 lq = make_uint4(lu[0], lu[1], lu[2], lu[3]);
    size_t rb = (size_t)row * K_EXT;
    *(uint4*)(dst + rb + seg * 8)            = hq;
    *(uint4*)(dst + rb + dupHiOff + seg * 8) = hq;
    *(uint4*)(dst + rb + loOff + seg * 8)    = lq;
}

// ---------------- kernel 3: mma.sync bf16 top-2 candidate search ----------------
// CTA = 128 threads (4 warps); each warp owns 32 rows (two 16-row A-tiles)
// so each B fragment is reused for 2 MMAs -> ~0.56x LDSM traffic vs R13.
__device__ __forceinline__ void am_load_stage(uint32_t smA, uint32_t smB,
                                              const char* XeB, const char* CeB,
                                              int rowbase, int cc, int kc, int tid) {
#pragma unroll
    for (int it = 0; it < 8; it++) {
        int idx = tid + 128 * it;
        int row = idx >> 3, seg = idx & 7;
        uint32_t off = (uint32_t)(row * 128 + seg * 16);
        cpa16(smA + SWZ128(off), XeB + (size_t)(rowbase + row) * ROWB + kc * 128 + seg * 16);
    }
#pragma unroll
    for (int it = 0; it < 8; it++) {
        int idx = tid + 128 * it;
        int row = idx >> 3, seg = idx & 7;
        uint32_t off = (uint32_t)(row * 128 + seg * 16);
        cpa16(smB + SWZ128(off), CeB + (size_t)(cc * 128 + row) * ROWB + kc * 128 + seg * 16);
    }
}

__global__ void __launch_bounds__(128)
argmin_mma_kernel(const unsigned short* __restrict__ Xe, const unsigned short* __restrict__ Ce,
                  const float* __restrict__ c2p,
                  float* __restrict__ cand0p, float* __restrict__ cand1p) {
    extern __shared__ char smc[];
    uint32_t sbase = smem_u32(smc);
    int tid = threadIdx.x;
    int lane = tid & 31, w = tid >> 5;           // w = 0..3
    int rowbase = blockIdx.x * 128;

    float* c2s = (float*)(smc + AM_C2);
    for (int i = tid; i < K_CODES; i += 128) c2s[i] = c2p[i];

    const char* XeB = (const char*)Xe;
    const char* CeB = (const char*)Ce;
    uint32_t smA[2] = { sbase + AM_A0, sbase + AM_A1 };
    uint32_t smB[2] = { sbase + AM_B0, sbase + AM_B1 };

    int g = lane >> 3;
    int arow_in = ((g & 1) ? 8 : 0) + (lane & 7);   // within 16-row A-tile
    uint32_t akoff = (g >= 2) ? 16u : 0u;
    int brow_base = ((g >= 2) ? 8 : 0) + (lane & 7);
    uint32_t bkoff = (uint32_t)((g & 1) * 16);

    // top-2 state for 4 owned rows: [at][half]  rows: 32w + 16*at + (lane>>2) + 8*half
    float bv[2][2], sv[2][2];
    int   bi[2][2], si[2][2];
#pragma unroll
    for (int at = 0; at < 2; at++)
#pragma unroll
        for (int h = 0; h < 2; h++) { bv[at][h] = 3.0e38f; sv[at][h] = 3.0e38f; bi[at][h] = 0; si[at][h] = 0; }

    for (int cc = 0; cc < 8; cc++) {
        float acc[2][16][4];
#pragma unroll
        for (int at = 0; at < 2; at++)
#pragma unroll
            for (int j = 0; j < 16; j++)
#pragma unroll
                for (int r = 0; r < 4; r++) acc[at][j][r] = 0.f;

        __syncthreads();
        am_load_stage(smA[0], smB[0], XeB, CeB, rowbase, cc, 0, tid);
        cpa_commit();

        for (int kc = 0; kc < 12; kc++) {
            cpa_wait0();
            __syncthreads();
            if (kc + 1 < 12) {
                am_load_stage(smA[(kc + 1) & 1], smB[(kc + 1) & 1], XeB, CeB, rowbase, cc, kc + 1, tid);
                cpa_commit();
            }
            uint32_t aT = smA[kc & 1], bT = smB[kc & 1];
#pragma unroll
            for (int ks = 0; ks < 4; ks++) {
                uint32_t a0[2], a1[2], a2[2], a3[2];
#pragma unroll
                for (int at = 0; at < 2; at++) {
                    int arow = 32 * w + 16 * at + arow_in;
                    uint32_t amask = (uint32_t)((arow & 7) * 16);
                    uint32_t aaddr = aT + (uint32_t)(arow * 128) + (((uint32_t)(ks * 32) + akoff) ^ amask);
                    LDSM4(a0[at], a1[at], a2[at], a3[at], aaddr);
                }
#pragma unroll
                for (int t = 0; t < 8; t++) {
                    int brow = 16 * t + brow_base;
                    uint32_t bmask = (uint32_t)((brow & 7) * 16);
                    uint32_t baddr = bT + (uint32_t)(brow * 128) + (((uint32_t)(ks * 32) + bkoff) ^ bmask);
                    uint32_t b0, b1, b2, b3;
                    LDSM4(b0, b1, b2, b3, baddr);
#pragma unroll
                    for (int at = 0; at < 2; at++) {
                        MMA16816(acc[at][2 * t],     a0[at], a1[at], a2[at], a3[at], b0, b1);
                        MMA16816(acc[at][2 * t + 1], a0[at], a1[at], a2[at], a3[at], b2, b3);
                    }
                }
            }
            __syncthreads();
        }

        // epilogue: v = c2[code] - 2*dot; top-2 update per owned row
        int colb = 2 * (lane & 3);
#pragma unroll
        for (int at = 0; at < 2; at++)
#pragma unroll
            for (int j = 0; j < 16; j++) {
                int code = cc * 128 + 8 * j + colb;
                float c2a = c2s[code], c2b = c2s[code + 1];
                top2_update(c2a - 2.0f * acc[at][j][0], code,     bv[at][0], bi[at][0], sv[at][0], si[at][0]);
                top2_update(c2b - 2.0f * acc[at][j][1], code + 1, bv[at][0], bi[at][0], sv[at][0], si[at][0]);
                top2_update(c2a - 2.0f * acc[at][j][2], code,     bv[at][1], bi[at][1], sv[at][1], si[at][1]);
                top2_update(c2b - 2.0f * acc[at][j][3], code + 1, bv[at][1], bi[at][1], sv[at][1], si[at][1]);
            }
    }

    // quad reduce top-2 (lanes sharing lane>>2 hold the same rows)
#pragma unroll
    for (int off = 1; off <= 2; off <<= 1) {
#pragma unroll
        for (int at = 0; at < 2; at++)
#pragma unroll
            for (int h = 0; h < 2; h++) {
                float obv = __shfl_xor_sync(0xFFFFFFFFu, bv[at][h], off);
                int   obi = __shfl_xor_sync(0xFFFFFFFFu, bi[at][h], off);
                float osv = __shfl_xor_sync(0xFFFFFFFFu, sv[at][h], off);
                int   osi = __shfl_xor_sync(0xFFFFFFFFu, si[at][h], off);
                top2_merge(obv, obi, osv, osi, bv[at][h], bi[at][h], sv[at][h], si[at][h]);
            }
    }

    if ((lane & 3) == 0) {
#pragma unroll
        for (int at = 0; at < 2; at++)
#pragma unroll
            for (int h = 0; h < 2; h++) {
                int r = rowbase + 32 * w + 16 * at + (lane >> 2) + 8 * h;
                cand0p[r] = (float)bi[at][h];
                cand1p[r] = (float)si[at][h];
            }
    }
}

// ---------------- kernel 4: exact fp32 fixup of top-2 candidates + vq partials ----------------
__global__ void __launch_bounds__(256)
fixup_kernel(const float* __restrict__ X, const float* __restrict__ C,
             const float* __restrict__ c2p, const float* __restrict__ x2p,
             const float* __restrict__ cand0p, const float* __restrict__ cand1p,
             float* __restrict__ partp, float* __restrict__ idxFp) {
    __shared__ float wsum[8];
    int lane = threadIdx.x & 31, w = threadIdx.x >> 5;
    int row = blockIdx.x * 8 + w;
    float contrib = 0.f;
    if (row < N_ROWS) {
        int c0 = (int)(cand0p[row] + 0.5f);
        int c1 = (int)(cand1p[row] + 0.5f);
        const float4* xr = (const float4*)(X + (size_t)row * D_DIM);
        const float4* a0 = (const float4*)(C + (size_t)c0 * D_DIM);
        const float4* a1 = (const float4*)(C + (size_t)c1 * D_DIM);
        float d0 = 0.f, d1 = 0.f;
#pragma unroll
        for (int i = 0; i < 2; i++) {
            float4 xv = xr[lane + 32 * i];
            float4 v0 = a0[lane + 32 * i];
            float4 v1 = a1[lane + 32 * i];
            d0 += xv.x * v0.x + xv.y * v0.y + xv.z * v0.z + xv.w * v0.w;
            d1 += xv.x * v1.x + xv.y * v1.y + xv.z * v1.z + xv.w * v1.w;
        }
#pragma unroll
        for (int o = 16; o; o >>= 1) {
            d0 += __shfl_xor_sync(0xFFFFFFFFu, d0, o);
            d1 += __shfl_xor_sync(0xFFFFFFFFu, d1, o);
        }
        float v0 = c2p[c0] - 2.0f * d0;
        float v1 = c2p[c1] - 2.0f * d1;
        int   bi = (v1 < v0 || (v1 == v0 && c1 < c0)) ? c1 : c0;
        float bv = (v1 < v0 || (v1 == v0 && c1 < c0)) ? v1 : v0;
        if (lane == 0) {
            idxFp[row] = (float)bi;
            contrib = x2p[row] + bv;
        }
    }
    if (lane == 0) wsum[w] = contrib;
    __syncthreads();
    if (threadIdx.x == 0) {
        float s = 0.f;
#pragma unroll
        for (int i = 0; i < 8; i++) s += wsum[i];
        partp[blockIdx.x] = s;
    }
}

// ---------------- kernel 5: vq_loss finalize ----------------
__global__ void __launch_bounds__(256)
finalize_kernel(const float* __restrict__ partp, float* __restrict__ lossp, int writeLoss) {
    __shared__ float s[256];
    int tid = threadIdx.x;
    float v = 0.f;
    for (int i = tid; i < NFIX_BLOCKS; i += 256) v += partp[i];
    s[tid] = v;
    __syncthreads();
    for (int o = 128; o >= 1; o >>= 1) {
        if (tid < o) s[tid] += s[tid + o];
        __syncthreads();
    }
    if (tid == 0 && writeLoss) {
        lossp[0] = 1.25f * s[0] / ((float)N_ROWS * (float)D_DIM);
    }
}

// ---------------- kernel 6: fused S-compute + gather (unchanged from R9) ----------------
__global__ void __launch_bounds__(256)
fused_score_kernel(const float* __restrict__ Qm, const float* __restrict__ Cm,
                   const float* __restrict__ idxFp, float* __restrict__ outp) {
    extern __shared__ float sm[];
    int tid = threadIdx.x;
    int qb = blockIdx.x * FQ;

#pragma unroll
    for (int it = 0; it < 4; it++) {
        int id = tid + 256 * it;
        int row = id >> 6;
        int c4 = id & 63;
        *(float4*)(sm + row * D_DIM + c4 * 4) =
            *(const float4*)(Qm + (size_t)(qb + row) * D_DIM + c4 * 4);
    }

    int qg = tid >> 7;
    int cg = tid & 127;
    int sw = cg & 3;

    float acc[8][8];
#pragma unroll
    for (int i = 0; i < 8; i++)
#pragma unroll
        for (int j = 0; j < 8; j++) acc[i][j] = 0.f;

    uint32_t bbase = smem_u32(sm + FS_AQ_F);

    for (int dc = 0; dc < D_DIM / 16; dc++) {
        __syncthreads();
#pragma unroll
        for (int it = 0; it < 16; it++) {
            int id = tid + 256 * it;
            int code = id >> 2;
            int dg = id & 3;
            int dsw = dg ^ ((code >> 3) & 3);
            cpa16(bbase + (uint32_t)(code * FS_BROW + dsw * 4) * 4,
                  Cm + (size_t)code * D_DIM + dc * 16 + dg * 4);
        }
        cpa_commit();
        cpa_wait0();
        __syncthreads();

        const float* Bb = sm + FS_AQ_F;
#pragma unroll
        for (int kk4 = 0; kk4 < 4; kk4++) {
            int ks = (kk4 ^ sw) << 2;
            float4 b4[8];
#pragma unroll
            for (int j = 0; j < 8; j++)
                b4[j] = *(const float4*)(Bb + (cg * 8 + j) * FS_BROW + ks);
#pragma unroll
            for (int i = 0; i < 8; i++) {
                float4 a4 = *(const float4*)(sm + (qg * 8 + i) * D_DIM + dc * 16 + kk4 * 4);
#pragma unroll
                for (int j = 0; j < 8; j++) {
                    acc[i][j] = fmaf(a4.x, b4[j].x, acc[i][j]);
                    acc[i][j] = fmaf(a4.y, b4[j].y, acc[i][j]);
                    acc[i][j] = fmaf(a4.z, b4[j].z, acc[i][j]);
                    acc[i][j] = fmaf(a4.w, b4[j].w, acc[i][j]);
                }
            }
        }
    }

    __syncthreads();
    float* S = sm + FS_AQ_F;
#pragma unroll
    for (int i = 0; i < 8; i++) {
#pragma unroll
        for (int j4 = 0; j4 < 2; j4++) {
            float4 v = make_float4(acc[i][j4 * 4 + 0], acc[i][j4 * 4 + 1],
                                   acc[i][j4 * 4 + 2], acc[i][j4 * 4 + 3]);
            *(float4*)(S + (qg * 8 + i) * K_CODES + cg * 8 + j4 * 4) = v;
        }
    }
    __syncthreads();

    for (int base = 0; base < N_ROWS; base += 1024) {
        int n = base + (tid << 2);
        if (n < N_ROWS) {
            int i0 = (int)(idxFp[n + 0] + 0.5f);
            int i1 = (int)(idxFp[n + 1] + 0.5f);
            int i2 = (int)(idxFp[n + 2] + 0.5f);
            int i3 = (int)(idxFp[n + 3] + 0.5f);
#pragma unroll
            for (int q = 0; q < FQ; q++) {
                const float* Sr = S + q * K_CODES;
                float4 v = make_float4(Sr[i0], Sr[i1], Sr[i2], Sr[i3]);
                *(float4*)(outp + (size_t)(qb + q) * N_ROWS + n) = v;
            }
        }
    }
}

// ---------------- host launch ----------------
extern "C" void kernel_launch(void* const* d_in, const int* in_sizes, int n_in,
                              void* d_out, int out_size) {
    const float* Qm = nullptr;
    const float* Xm = nullptr;
    const float* Cm = nullptr;
    for (int i = 0; i < n_in; i++) {
        if (in_sizes[i] == Q_ROWS * D_DIM)       Qm = (const float*)d_in[i];
        else if (in_sizes[i] == N_ROWS * D_DIM)  Xm = (const float*)d_in[i];
        else if (in_sizes[i] == K_CODES * D_DIM) Cm = (const float*)d_in[i];
    }
    if (!Qm && n_in > 0) Qm = (const float*)d_in[0];
    if (!Xm && n_in > 1) Xm = (const float*)d_in[1];
    if (!Cm && n_in > 2) Cm = (const float*)d_in[2];

    float* out = (float*)d_out;
    bool hasExtra = ((size_t)out_size >= QN + 1 + N_ROWS);

    // Scratch carved from the score region (overwritten last by fused_score):
    float* c2p    = out;                  // [0, 1024)
    float* x2p    = out + 2048;           // [2048, 52048)
    unsigned short* Xe = (unsigned short*)(out + XE_OFF_F);
    unsigned short* Ce = (unsigned short*)(out + CE_OFF_F);
    float* cand0p = out + CAND0_OFF_F;
    float* cand1p = out + CAND1_OFF_F;
    float* partp  = out + PART_OFF_F;
    float* idxp   = hasExtra ? (out + QN + 1) : (out + (QN - N_ROWS));
    float* lossp  = out + QN;

    (void)cudaFuncSetAttribute(argmin_mma_kernel,  cudaFuncAttributeMaxDynamicSharedMemorySize, AM_SMEM_B);
    (void)cudaFuncSetAttribute(fused_score_kernel, cudaFuncAttributeMaxDynamicSharedMemorySize, FS_SMEM_B);

    // 1. norms
    rownorm_kernel<<<(K_CODES + 7) / 8, 256>>>(Cm, K_CODES, c2p);
    rownorm_kernel<<<(N_ROWS + 7) / 8, 256>>>(Xm, N_ROWS, x2p);

    // 2. bf16 hi/lo split conversions: X -> [hi|hi|lo], C -> [hi|lo|hi]
    convert_kernel<<<(XE_ROWS * 32 + 255) / 256, 256>>>(Xm, Xe, N_ROWS, XE_ROWS, 256, 512);
    convert_kernel<<<(K_CODES * 32 + 255) / 256, 256>>>(Cm, Ce, K_CODES, K_CODES, 512, 256);

    // 3. mma.sync top-2 candidate search (4 warps x 32 rows, B-frag reuse x2)
    argmin_mma_kernel<<<NTILES_N, 128, AM_SMEM_B>>>(Xe, Ce, c2p, cand0p, cand1p);

    // 4. exact fp32 fixup -> nearest_idx + vq partials
    fixup_kernel<<<NFIX_BLOCKS, 256>>>(Xm, Cm, c2p, x2p, cand0p, cand1p, partp, idxp);

    // 5. vq_loss
    finalize_kernel<<<1, 256>>>(partp, lossp, hasExtra ? 1 : 0);

    // 6. fused S = Q@C^T + score gather (overwrites all scratch)
    fused_score_kernel<<<Q_ROWS / FQ, 256, FS_SMEM_B>>>(Qm, Cm, idxp, out);
}